// round 13
// baseline (speedup 1.0000x reference)
#include <cuda_runtime.h>
#include <cuda_fp16.h>
#include <math_constants.h>

#define NB 128
#define N 1024
#define NITERS 20
#define GROUP 32
#define NGROUPS (NB / GROUP)
#define RPB 16
#define BPB (N / RPB)            // 64 blocks per batch
#define LOG2E 1.44269504088896340736f

// h1 = s - R1 in fp16 (log2 domain), R1 exact in registers at init.
// Shifted-domain updates: Rr^t = Rr^{t-1} + log2 rowsum(e'), with
// e' = 2^(h - Cr^{t-1} - Rr^{t-1}) <= 1 (elementwise, by the col-LSE bound),
// and Cr^t = Cr^{t-1} + log2 sum_i e'_ij / rowsum'_i  — ONE exp, ONE matrix
// read per full iteration.
static __device__ __half g_h[(size_t)NB * N * N];    // 256 MB
static __device__ float g_Rr[NB * N], g_Cr[NB * N];
static __device__ float g_part[GROUP][BPB][N];       // 8 MB col partials

__device__ __forceinline__ float ex2(float x) {
    float y;
    asm("ex2.approx.ftz.f32 %0, %1;" : "=f"(y) : "f"(x));
    return y;
}

// ---------------------------------------------------------------------------
// FUSED init + iter-1 row pass: Gumbel transform in registers (accurate logf
// inner), exact row max+LSE -> R1, write h1 = half(s - R1), Rr = 0.
// ---------------------------------------------------------------------------
__global__ void __launch_bounds__(256) gs_init_row(const float* __restrict__ la,
                                                   const float* __restrict__ noise,
                                                   int b0) {
    const float EPS = 1e-20f;
    const float SC = 10.0f * LOG2E;
    int lane = threadIdx.x & 31, w = threadIdx.x >> 5;
    int rglob = b0 * N + blockIdx.x * 8 + w;
    const float4* __restrict__ arow =
        reinterpret_cast<const float4*>(la + (size_t)rglob * N);
    const float4* __restrict__ urow =
        reinterpret_cast<const float4*>(noise + (size_t)rglob * N);

    float4 sv[8];
#pragma unroll
    for (int k = 0; k < 8; k++) {
        float4 a = arow[k * 32 + lane];
        float4 u = urow[k * 32 + lane];
        sv[k].x = (a.x - __logf(EPS - logf(u.x + EPS))) * SC;
        sv[k].y = (a.y - __logf(EPS - logf(u.y + EPS))) * SC;
        sv[k].z = (a.z - __logf(EPS - logf(u.z + EPS))) * SC;
        sv[k].w = (a.w - __logf(EPS - logf(u.w + EPS))) * SC;
    }
    float m = -CUDART_INF_F;
#pragma unroll
    for (int k = 0; k < 8; k++)
        m = fmaxf(m, fmaxf(fmaxf(sv[k].x, sv[k].y), fmaxf(sv[k].z, sv[k].w)));
#pragma unroll
    for (int o = 16; o; o >>= 1) m = fmaxf(m, __shfl_xor_sync(~0u, m, o));
    float a0 = 0.f, a1 = 0.f;
#pragma unroll
    for (int k = 0; k < 8; k++) {
        a0 += ex2(sv[k].x - m) + ex2(sv[k].y - m);
        a1 += ex2(sv[k].z - m) + ex2(sv[k].w - m);
    }
    float sum = a0 + a1;
#pragma unroll
    for (int o = 16; o; o >>= 1) sum += __shfl_xor_sync(~0u, sum, o);
    float r1 = m + __log2f(sum);

    uint2* __restrict__ hrow = reinterpret_cast<uint2*>(g_h + (size_t)rglob * N);
#pragma unroll
    for (int k = 0; k < 8; k++) {
        __half2 h01 = __floats2half2_rn(sv[k].x - r1, sv[k].y - r1);
        __half2 h23 = __floats2half2_rn(sv[k].z - r1, sv[k].w - r1);
        uint2 pv;
        pv.x = *reinterpret_cast<unsigned*>(&h01);
        pv.y = *reinterpret_cast<unsigned*>(&h23);
        hrow[k * 32 + lane] = pv;
    }
    if (lane == 0) g_Rr[rglob] = 0.0f;
}

// ---------------------------------------------------------------------------
// Iter-1 col pass: Cr^1 = log2 sum_i 2^(h - Rr_i), Rr = 0. Runs once/group.
// ---------------------------------------------------------------------------
__global__ void __launch_bounds__(512) gs_col_h(int b0) {
    __shared__ float sr[N];
    __shared__ float part[16][66];
    int tid = threadIdx.x, lane = tid & 31, w = tid >> 5;
    int b = b0 + blockIdx.y;
    int j0 = blockIdx.x * 64;
    if (tid < 256)
        reinterpret_cast<float4*>(sr)[tid] =
            reinterpret_cast<const float4*>(g_Rr + (size_t)b * N)[tid];
    __syncthreads();

    const __half2* __restrict__ hp =
        reinterpret_cast<const __half2*>(g_h + (size_t)b * N * N + j0) + lane;
    int i0 = w * 64;
    float ax = 0.f, ay = 0.f;
#pragma unroll
    for (int ii = 0; ii < 64; ii += 8) {
        __half2 v[8];
#pragma unroll
        for (int q = 0; q < 8; q++) v[q] = hp[(size_t)(i0 + ii + q) * (N / 2)];
#pragma unroll
        for (int q = 0; q < 8; q++) {
            float rr = sr[i0 + ii + q];
            float2 f = __half22float2(v[q]);
            ax += ex2(f.x - rr);
            ay += ex2(f.y - rr);
        }
    }
    part[w][2 * lane] = ax;
    part[w][2 * lane + 1] = ay;
    __syncthreads();
    if (tid < 64) {
        float t = 0.f;
#pragma unroll
        for (int k = 0; k < 16; k++) t += part[k][tid];
        g_Cr[(size_t)b * N + j0 + tid] = __log2f(t);
    }
}

// ---------------------------------------------------------------------------
// FUSED iteration kernel (row + col in ONE matrix read, ONE exp/element).
// Block = 16 rows of one batch, 512 thr (warp per row).
//  pass1: e' = 2^(h - Cr - Rr_prev) <= 1; band (fp16) in SMEM;
//         Rr_new = Rr_prev + log2(rowsum'); sinv = 1/rowsum'.
//  pass2: warp w -> cols [64w,64w+64): partial_j = sum_i band[i][j]*sinv[i]
//         (= 2^{-Cr_j} * sum_i 2^(h - Rr_new_i)) -> fixed global slot.
// ---------------------------------------------------------------------------
__global__ void __launch_bounds__(512) gs_fused(int b0) {
    __shared__ __half band[RPB][N];   // 32 KB
    __shared__ float scr[N];          // 4 KB  (Cr staged)
    __shared__ float sinv[RPB];
    int tid = threadIdx.x, lane = tid & 31, w = tid >> 5;
    int bl = blockIdx.x >> 6;
    int blk = blockIdx.x & 63;
    int b = b0 + bl;
    int row = blk * RPB + w;

    reinterpret_cast<float2*>(scr)[tid] =
        reinterpret_cast<const float2*>(g_Cr + (size_t)b * N)[tid];
    __syncthreads();

    float rprev = g_Rr[(size_t)b * N + row];
    const uint4* __restrict__ hrow =
        reinterpret_cast<const uint4*>(g_h + ((size_t)b * N + row) * N);
    uint4* brow = reinterpret_cast<uint4*>(&band[w][0]);
    const float4* scv = reinterpret_cast<const float4*>(scr);

    float a0 = 0.f, a1 = 0.f;
#pragma unroll
    for (int k = 0; k < 4; k++) {
        int i = k * 32 + lane;
        uint4 hv = hrow[i];
        float4 c0 = scv[2 * i], c1 = scv[2 * i + 1];
        float2 f0 = __half22float2(*reinterpret_cast<__half2*>(&hv.x));
        float2 f1 = __half22float2(*reinterpret_cast<__half2*>(&hv.y));
        float2 f2 = __half22float2(*reinterpret_cast<__half2*>(&hv.z));
        float2 f3 = __half22float2(*reinterpret_cast<__half2*>(&hv.w));
        float e0 = ex2(f0.x - c0.x - rprev), e1 = ex2(f0.y - c0.y - rprev);
        float e2 = ex2(f1.x - c0.z - rprev), e3 = ex2(f1.y - c0.w - rprev);
        float e4 = ex2(f2.x - c1.x - rprev), e5 = ex2(f2.y - c1.y - rprev);
        float e6 = ex2(f3.x - c1.z - rprev), e7 = ex2(f3.y - c1.w - rprev);
        a0 += (e0 + e1) + (e2 + e3);
        a1 += (e4 + e5) + (e6 + e7);
        __half2 p01 = __floats2half2_rn(e0, e1);
        __half2 p23 = __floats2half2_rn(e2, e3);
        __half2 p45 = __floats2half2_rn(e4, e5);
        __half2 p67 = __floats2half2_rn(e6, e7);
        uint4 ev;
        ev.x = *reinterpret_cast<unsigned*>(&p01);
        ev.y = *reinterpret_cast<unsigned*>(&p23);
        ev.z = *reinterpret_cast<unsigned*>(&p45);
        ev.w = *reinterpret_cast<unsigned*>(&p67);
        brow[i] = ev;
    }
    float sum = a0 + a1;
#pragma unroll
    for (int o = 16; o; o >>= 1) sum += __shfl_xor_sync(~0u, sum, o);
    if (lane == 0) {
        sinv[w] = 1.0f / sum;
        g_Rr[(size_t)b * N + row] = rprev + __log2f(sum);
    }
    __syncthreads();

    // pass 2: warp w owns cols [64w, 64w+64), lane -> 2 cols (half2).
    int j = w * 64 + 2 * lane;
    float ax = 0.f, ay = 0.f;
#pragma unroll
    for (int i = 0; i < RPB; i++) {
        float iv = sinv[i];
        float2 f = __half22float2(*reinterpret_cast<const __half2*>(&band[i][j]));
        ax = fmaf(f.x, iv, ax);
        ay = fmaf(f.y, iv, ay);
    }
    float2 o;
    o.x = ax; o.y = ay;
    *reinterpret_cast<float2*>(&g_part[bl][blk][j]) = o;
}

// ---------------------------------------------------------------------------
// Deterministic col finalize: Cr += log2(sum over the 64 fixed partial slots).
// ---------------------------------------------------------------------------
__global__ void __launch_bounds__(256) gs_reduce(int b0) {
    int bl = blockIdx.y;
    int j = blockIdx.x * 256 + threadIdx.x;
    float t = 0.f;
#pragma unroll 8
    for (int k = 0; k < BPB; k++) t += g_part[bl][k][j];
    size_t cj = (size_t)(b0 + bl) * N + j;
    g_Cr[cj] += __log2f(fmaxf(t, 1e-30f));
}

// ---------------------------------------------------------------------------
// Final: out = 2^(h - Rr - Cr).
// ---------------------------------------------------------------------------
__global__ void __launch_bounds__(256) gs_final(float* __restrict__ out, int b0) {
    size_t t8 = (size_t)blockIdx.x * 256 + threadIdx.x;
    size_t e = (size_t)b0 * N * N + t8 * 8;
    int row = (int)(e >> 10);
    int b = row >> 10;
    int j = (int)(e & (N - 1));
    float r = g_Rr[row];
    float4 c0 = *reinterpret_cast<const float4*>(g_Cr + (size_t)b * N + j);
    float4 c1 = *reinterpret_cast<const float4*>(g_Cr + (size_t)b * N + j + 4);
    uint4 hv = __ldcs(reinterpret_cast<const uint4*>(g_h + e));
    float2 f0 = __half22float2(*reinterpret_cast<__half2*>(&hv.x));
    float2 f1 = __half22float2(*reinterpret_cast<__half2*>(&hv.y));
    float2 f2 = __half22float2(*reinterpret_cast<__half2*>(&hv.z));
    float2 f3 = __half22float2(*reinterpret_cast<__half2*>(&hv.w));
    float4 o0, o1;
    o0.x = ex2(f0.x - r - c0.x); o0.y = ex2(f0.y - r - c0.y);
    o0.z = ex2(f1.x - r - c0.z); o0.w = ex2(f1.y - r - c0.w);
    o1.x = ex2(f2.x - r - c1.x); o1.y = ex2(f2.y - r - c1.y);
    o1.z = ex2(f3.x - r - c1.z); o1.w = ex2(f3.y - r - c1.w);
    *reinterpret_cast<float4*>(out + e) = o0;
    *reinterpret_cast<float4*>(out + e + 4) = o1;
}

// ---------------------------------------------------------------------------
// 4 groups of 32 batches. Per iteration: ONE 64 MB matrix read + one exp per
// element (fused) + an 8 MB deterministic partial reduce.
// ---------------------------------------------------------------------------
extern "C" void kernel_launch(void* const* d_in, const int* in_sizes, int n_in,
                              void* d_out, int out_size) {
    const float* la = (const float*)d_in[0];
    const float* noise = (const float*)d_in[1];
    float* out = (float*)d_out;

    for (int g = 0; g < NGROUPS; g++) {
        int b0 = g * GROUP;
        gs_init_row<<<(GROUP * N) / 8, 256>>>(la, noise, b0);  // row 1 + pack
        gs_col_h<<<dim3(N / 64, GROUP), 512>>>(b0);            // col 1 (Rr=0)
        for (int t = 2; t <= NITERS; t++) {
            gs_fused<<<GROUP * BPB, 512>>>(b0);                // row t + partials
            gs_reduce<<<dim3(N / 256, GROUP), 256>>>(b0);      // col t
        }
        gs_final<<<(GROUP * N * N) / (256 * 8), 256>>>(out, b0);
    }
}